// round 16
// baseline (speedup 1.0000x reference)
#include <cuda_runtime.h>
#include <math.h>

#define NMAX 50000
#define FDIM 96
#define FD4  24          // float4s per feature row
#define EMAX 800000
#define DEPTH 3
#define OUTC 384         // (DEPTH+1)*FDIM
#define LEAKY 0.2f
#define SMW  64          // smem weight slots per warp (deg <= SMW fast path)
#define CAP  96          // padded CSR slots per row (Poisson(16): P(>96) ~ 1e-40)

// packed f32x2 helpers (sm_103a): one instruction = two independent fp32 FMAs
#define PACK2(d, x, y) \
    asm("mov.b64 %0, {%1, %2};" : "=l"(d) : "f"(x), "f"(y))
#define UNPACK2(x, y, d) \
    asm("mov.b64 {%0, %1}, %2;" : "=f"(x), "=f"(y) : "l"(d))
#define FMA2(d, a, b, c) \
    asm("fma.rn.f32x2 %0, %1, %2, %3;" : "=l"(d) : "l"(a), "l"(b), "l"(c))

// ---------------- device scratch ----------------
__device__ float4 g_fa[NMAX * FD4];
__device__ float4 g_fb[NMAX * FD4];
__device__ float4 g_et_a[NMAX];               // eterm ping
__device__ float4 g_et_b[NMAX];               // eterm pong
__device__ float4 g_scbig[(NMAX * CAP) / 2];  // fallback weights, full padded space
__device__ int    g_deg[NMAX];
__device__ int    g_csrcol[NMAX * CAP];       // padded CSR (16B-aligned rows)
__device__ int    g_overflow;

__device__ __forceinline__ float leaky(float x) {
    return x > 0.0f ? x : LEAKY * x;
}

// Per-block int64-vs-int32 detection (odd words of int64 < 2^31 are all 0).
__device__ __forceinline__ int block_is64(const int* __restrict__ words,
                                          int nwords) {
    __shared__ int s_flag;
    if (threadIdx.x == 0) {
        int acc = 0;
        int lim = min(nwords, 128);
        for (int i = 1; i < lim; i += 2) acc |= words[i];
        s_flag = (acc == 0) ? 1 : 0;
    }
    __syncthreads();
    return s_flag;
}

// compute 4 attention dots from a register-resident feature float4 (lane<FD4)
__device__ __forceinline__ void eterm_from_regs(
    float4* __restrict__ et, int row, float4 f, bool act, int lane,
    const float4* __restrict__ as4, const float4* __restrict__ an4) {
    float s0 = 0.f, s1 = 0.f, n0 = 0.f, n1 = 0.f;
    if (act) {
        float4 a;
        a = as4[lane];        s0 = f.x*a.x + f.y*a.y + f.z*a.z + f.w*a.w;
        a = as4[FD4 + lane];  s1 = f.x*a.x + f.y*a.y + f.z*a.z + f.w*a.w;
        a = an4[lane];        n0 = f.x*a.x + f.y*a.y + f.z*a.z + f.w*a.w;
        a = an4[FD4 + lane];  n1 = f.x*a.x + f.y*a.y + f.z*a.z + f.w*a.w;
    }
#pragma unroll
    for (int off = 16; off > 0; off >>= 1) {
        s0 += __shfl_xor_sync(0xffffffffu, s0, off);
        s1 += __shfl_xor_sync(0xffffffffu, s1, off);
        n0 += __shfl_xor_sync(0xffffffffu, n0, off);
        n1 += __shfl_xor_sync(0xffffffffu, n1, off);
    }
    if (lane == 0) et[row] = make_float4(s0, s1, n0, n1);
}

// ---------------- zero deg ----------------
__global__ void k_zero(int n) {
    int gid = blockIdx.x * blockDim.x + threadIdx.x;
    for (int i = gid; i < n; i += gridDim.x * blockDim.x)
        g_deg[i] = 0;
    if (gid == 0) g_overflow = 0;
}

// ---------------- direct padded-CSR scatter (single pass) ----------------
__global__ void k_scatter(const void* __restrict__ adj, int e, int n) {
    int is64 = block_is64((const int*)adj, 2 * e * 2);
    for (int i = blockIdx.x * blockDim.x + threadIdx.x; i < e;
         i += gridDim.x * blockDim.x) {
        int r, c;
        if (is64) {
            longlong2 rc = ((const longlong2*)adj)[i];
            r = (int)rc.x; c = (int)rc.y;
        } else {
            int2 rc = ((const int2*)adj)[i];
            r = rc.x; c = rc.y;
        }
        if ((unsigned)r >= (unsigned)n) continue;
        if ((unsigned)c >= (unsigned)n) c = 0;
        int pos = atomicAdd(&g_deg[r], 1);
        if (pos < CAP) g_csrcol[r * CAP + pos] = c;
        else atomicAdd(&g_overflow, 1);
    }
}

// ---------------- initial features + fused eterm (writes et_a) ------------
__global__ void k_init(const float* __restrict__ node_f,
                       const void* __restrict__ sidx,
                       const float* __restrict__ sval,
                       const float* __restrict__ as, const float* __restrict__ an,
                       float* __restrict__ out, int n) {
    int is64 = block_is64((const int*)sidx, 2 * n * 2);
    int gw = (blockIdx.x * blockDim.x + threadIdx.x) >> 5;
    int lane = threadIdx.x & 31;
    if (gw >= n) return;
    int r, c;
    if (is64) {
        longlong2 rc = ((const longlong2*)sidx)[gw];
        r = (int)rc.x; c = (int)rc.y;
    } else {
        int2 rc = ((const int2*)sidx)[gw];
        r = rc.x; c = rc.y;
    }
    if ((unsigned)r >= (unsigned)n || (unsigned)c >= (unsigned)n) return;
    bool act = (lane < FD4);
    float v = sval[gw];
    float4 x = make_float4(0.f, 0.f, 0.f, 0.f);
    if (act) {
        float4 s = ((const float4*)node_f)[(long)c * FD4 + lane];
        x.x = fmaxf(v * s.x, 0.0f);
        x.y = fmaxf(v * s.y, 0.0f);
        x.z = fmaxf(v * s.z, 0.0f);
        x.w = fmaxf(v * s.w, 0.0f);
        g_fa[(long)r * FD4 + lane] = x;
        ((float4*)(out + (long)r * OUTC))[lane] = x;
    }
    eterm_from_regs(g_et_a, r, x, act, lane, (const float4*)as, (const float4*)an);
}

// ---------------- layer: direct-exp softmax + aggregate + fused eterm -----
__global__ void __launch_bounds__(256) k_layer(int src, float* __restrict__ out,
                                               const float* __restrict__ as,
                                               const float* __restrict__ an,
                                               int layer, int n) {
    __shared__ float4 s_w4[8][SMW / 2];   // 8 warps x 32 float4 = 4KB
    int wslot = (threadIdx.x >> 5);
    int gw = (blockIdx.x * blockDim.x + threadIdx.x) >> 5;
    int lane = threadIdx.x & 31;
    if (gw >= n) return;
    const float4* feat  = src ? g_fb : g_fa;
    float4* feat_out    = src ? g_fa : g_fb;
    const float4* et_in = src ? g_et_b : g_et_a;
    float4* et_out      = src ? g_et_a : g_et_b;

    int start = gw * CAP;
    int deg   = min(g_deg[gw], CAP);
    int end   = start + deg;
    bool small = (deg <= SMW);

    float4 er = et_in[gw];
    float es0 = er.x, es1 = er.y;

    // pass 1: gather eterm, exp(leaky(score)) -> smem (or g_scbig) + sums
    float sum0 = 0.0f, sum1 = 0.0f;
    {
        float2* sw2 = (float2*)s_w4[wslot];
        float2* sb2 = (float2*)g_scbig;
        for (int j = start + lane; j < end; j += 32) {
            int c = g_csrcol[j];
            float4 ec = et_in[c];
            float w0 = __expf(leaky(es0 + ec.z));
            float w1 = __expf(leaky(es1 + ec.w));
            if (small) sw2[j - start] = make_float2(w0, w1);
            else       sb2[j] = make_float2(w0, w1);
            sum0 += w0;
            sum1 += w1;
        }
    }
#pragma unroll
    for (int off = 16; off > 0; off >>= 1) {
        sum0 += __shfl_xor_sync(0xffffffffu, sum0, off);
        sum1 += __shfl_xor_sync(0xffffffffu, sum1, off);
    }
    float inv0 = sum0 > 0.0f ? 1.0f / sum0 : 0.0f;
    float inv1 = sum1 > 0.0f ? 1.0f / sum1 : 0.0f;
    __syncwarp();

    // pass 2: weighted aggregation, 4 edges in flight, packed f32x2 FMAs
    unsigned long long A0xy = 0ull, A0zw = 0ull, A1xy = 0ull, A1zw = 0ull;
    bool act = (lane < FD4);

    int j = start;
    int iw = 0;
    for (; j + 4 <= end; j += 4, iw += 2) {
        int4 cc = *(const int4*)&g_csrcol[j];
        float4 wA, wB;                     // (w0e0,w1e0,w0e1,w1e1),(e2,e3)
        if (small) {
            wA = s_w4[wslot][iw];
            wB = s_w4[wslot][iw + 1];
        } else {
            wA = g_scbig[(j >> 1)];
            wB = g_scbig[(j >> 1) + 1];
        }
        float4 f0 = make_float4(0.f,0.f,0.f,0.f), f1 = f0, f2 = f0, f3 = f0;
        if (act) {
            f0 = feat[(long)cc.x * FD4 + lane];
            f1 = feat[(long)cc.y * FD4 + lane];
            f2 = feat[(long)cc.z * FD4 + lane];
            f3 = feat[(long)cc.w * FD4 + lane];
        }
        unsigned long long w0d, w1d, fxy, fzw;
        // edge 0: weights wA.x (h0), wA.y (h1)
        PACK2(w0d, wA.x, wA.x); PACK2(w1d, wA.y, wA.y);
        PACK2(fxy, f0.x, f0.y); PACK2(fzw, f0.z, f0.w);
        FMA2(A0xy, w0d, fxy, A0xy); FMA2(A0zw, w0d, fzw, A0zw);
        FMA2(A1xy, w1d, fxy, A1xy); FMA2(A1zw, w1d, fzw, A1zw);
        // edge 1: wA.z, wA.w
        PACK2(w0d, wA.z, wA.z); PACK2(w1d, wA.w, wA.w);
        PACK2(fxy, f1.x, f1.y); PACK2(fzw, f1.z, f1.w);
        FMA2(A0xy, w0d, fxy, A0xy); FMA2(A0zw, w0d, fzw, A0zw);
        FMA2(A1xy, w1d, fxy, A1xy); FMA2(A1zw, w1d, fzw, A1zw);
        // edge 2: wB.x, wB.y
        PACK2(w0d, wB.x, wB.x); PACK2(w1d, wB.y, wB.y);
        PACK2(fxy, f2.x, f2.y); PACK2(fzw, f2.z, f2.w);
        FMA2(A0xy, w0d, fxy, A0xy); FMA2(A0zw, w0d, fzw, A0zw);
        FMA2(A1xy, w1d, fxy, A1xy); FMA2(A1zw, w1d, fzw, A1zw);
        // edge 3: wB.z, wB.w
        PACK2(w0d, wB.z, wB.z); PACK2(w1d, wB.w, wB.w);
        PACK2(fxy, f3.x, f3.y); PACK2(fzw, f3.z, f3.w);
        FMA2(A0xy, w0d, fxy, A0xy); FMA2(A0zw, w0d, fzw, A0zw);
        FMA2(A1xy, w1d, fxy, A1xy); FMA2(A1zw, w1d, fzw, A1zw);
    }
    for (; j < end; j++) {
        int c0 = g_csrcol[j];
        float2 w0 = small ? ((float2*)s_w4[wslot])[j - start]
                          : ((float2*)g_scbig)[j];
        float4 f0 = make_float4(0.f,0.f,0.f,0.f);
        if (act) f0 = feat[(long)c0 * FD4 + lane];
        unsigned long long w0d, w1d, fxy, fzw;
        PACK2(w0d, w0.x, w0.x); PACK2(w1d, w0.y, w0.y);
        PACK2(fxy, f0.x, f0.y); PACK2(fzw, f0.z, f0.w);
        FMA2(A0xy, w0d, fxy, A0xy); FMA2(A0zw, w0d, fzw, A0zw);
        FMA2(A1xy, w1d, fxy, A1xy); FMA2(A1zw, w1d, fzw, A1zw);
    }

    float4 A0, A1;
    UNPACK2(A0.x, A0.y, A0xy); UNPACK2(A0.z, A0.w, A0zw);
    UNPACK2(A1.x, A1.y, A1xy); UNPACK2(A1.z, A1.w, A1zw);

    float4 v = make_float4(0.f, 0.f, 0.f, 0.f);
    if (act) {
        v.x = fmaxf(0.5f * (A0.x * inv0 + A1.x * inv1), 0.0f);
        v.y = fmaxf(0.5f * (A0.y * inv0 + A1.y * inv1), 0.0f);
        v.z = fmaxf(0.5f * (A0.z * inv0 + A1.z * inv1), 0.0f);
        v.w = fmaxf(0.5f * (A0.w * inv0 + A1.w * inv1), 0.0f);
        feat_out[(long)gw * FD4 + lane] = v;
        ((float4*)(out + (long)gw * OUTC + (layer + 1) * FDIM))[lane] = v;
    }
    if (layer + 1 < DEPTH)
        eterm_from_regs(et_out, gw, v, act, lane,
                        (const float4*)as, (const float4*)an);
}

// ---------------- launch ----------------
extern "C" void kernel_launch(void* const* d_in, const int* in_sizes, int n_in,
                              void* d_out, int out_size) {
    const float* node_f = (const float*)d_in[0];
    const void*  adj    = d_in[1];
    const void*  sidx   = d_in[2];
    const float* sval   = (const float*)d_in[3];
    const float* as_k   = (const float*)d_in[4];
    const float* an_k   = (const float*)d_in[5];
    float*       out    = (float*)d_out;

    int n = in_sizes[0] / FDIM;
    int e = in_sizes[1] / 2;
    if (n > NMAX) n = NMAX;
    if (e > EMAX) e = EMAX;

    const int T = 256;
    int gridN = (n + T - 1) / T;
    int gridE = (e + T - 1) / T;
    int gridW = (n + (T / 32) - 1) / (T / 32);

    k_zero<<<gridN, T>>>(n);
    k_scatter<<<gridE, T>>>(adj, e, n);
    k_init<<<gridW, T>>>(node_f, sidx, sval, as_k, an_k, out, n);

    int src = 0;
    for (int d = 0; d < DEPTH; d++) {
        k_layer<<<gridW, T>>>(src, out, as_k, an_k, d, n);
        src ^= 1;
    }
}

// round 17
// speedup vs baseline: 1.2154x; 1.2154x over previous
#include <cuda_runtime.h>
#include <math.h>

#define NMAX 50000
#define FDIM 96
#define FD4  24          // float4s per feature row
#define EMAX 800000
#define DEPTH 3
#define OUTC 384         // (DEPTH+1)*FDIM
#define LEAKY 0.2f
#define SMW  64          // smem weight slots per warp (deg <= SMW fast path)
#define CAP  96          // padded CSR slots per row (Poisson(16): P(>96) ~ 1e-40)

// ---------------- device scratch ----------------
__device__ float4 g_fa[NMAX * FD4];
__device__ float4 g_fb[NMAX * FD4];
__device__ float4 g_et_a[NMAX];               // eterm ping
__device__ float4 g_et_b[NMAX];               // eterm pong
__device__ float4 g_scbig[(NMAX * CAP) / 2];  // fallback weights, full padded space
__device__ int    g_deg[NMAX];
__device__ int    g_csrcol[NMAX * CAP];       // padded CSR (16B-aligned rows)
__device__ int    g_overflow;

__device__ __forceinline__ float leaky(float x) {
    return x > 0.0f ? x : LEAKY * x;
}

// Per-block int64-vs-int32 detection (odd words of int64 < 2^31 are all 0).
__device__ __forceinline__ int block_is64(const int* __restrict__ words,
                                          int nwords) {
    __shared__ int s_flag;
    if (threadIdx.x == 0) {
        int acc = 0;
        int lim = min(nwords, 128);
        for (int i = 1; i < lim; i += 2) acc |= words[i];
        s_flag = (acc == 0) ? 1 : 0;
    }
    __syncthreads();
    return s_flag;
}

// compute 4 attention dots from a register-resident feature float4 (lane<FD4)
__device__ __forceinline__ void eterm_from_regs(
    float4* __restrict__ et, int row, float4 f, bool act, int lane,
    const float4* __restrict__ as4, const float4* __restrict__ an4) {
    float s0 = 0.f, s1 = 0.f, n0 = 0.f, n1 = 0.f;
    if (act) {
        float4 a;
        a = as4[lane];        s0 = f.x*a.x + f.y*a.y + f.z*a.z + f.w*a.w;
        a = as4[FD4 + lane];  s1 = f.x*a.x + f.y*a.y + f.z*a.z + f.w*a.w;
        a = an4[lane];        n0 = f.x*a.x + f.y*a.y + f.z*a.z + f.w*a.w;
        a = an4[FD4 + lane];  n1 = f.x*a.x + f.y*a.y + f.z*a.z + f.w*a.w;
    }
#pragma unroll
    for (int off = 16; off > 0; off >>= 1) {
        s0 += __shfl_xor_sync(0xffffffffu, s0, off);
        s1 += __shfl_xor_sync(0xffffffffu, s1, off);
        n0 += __shfl_xor_sync(0xffffffffu, n0, off);
        n1 += __shfl_xor_sync(0xffffffffu, n1, off);
    }
    if (lane == 0) et[row] = make_float4(s0, s1, n0, n1);
}

// ---------------- zero deg ----------------
__global__ void k_zero(int n) {
    int gid = blockIdx.x * blockDim.x + threadIdx.x;
    for (int i = gid; i < n; i += gridDim.x * blockDim.x)
        g_deg[i] = 0;
    if (gid == 0) g_overflow = 0;
}

// ---------------- direct padded-CSR scatter (single pass) ----------------
__global__ void k_scatter(const void* __restrict__ adj, int e, int n) {
    int is64 = block_is64((const int*)adj, 2 * e * 2);
    for (int i = blockIdx.x * blockDim.x + threadIdx.x; i < e;
         i += gridDim.x * blockDim.x) {
        int r, c;
        if (is64) {
            longlong2 rc = ((const longlong2*)adj)[i];
            r = (int)rc.x; c = (int)rc.y;
        } else {
            int2 rc = ((const int2*)adj)[i];
            r = rc.x; c = rc.y;
        }
        if ((unsigned)r >= (unsigned)n) continue;
        if ((unsigned)c >= (unsigned)n) c = 0;
        int pos = atomicAdd(&g_deg[r], 1);
        if (pos < CAP) g_csrcol[r * CAP + pos] = c;
        else atomicAdd(&g_overflow, 1);
    }
}

// ---------------- initial features + fused eterm (writes et_a) ------------
__global__ void k_init(const float* __restrict__ node_f,
                       const void* __restrict__ sidx,
                       const float* __restrict__ sval,
                       const float* __restrict__ as, const float* __restrict__ an,
                       float* __restrict__ out, int n) {
    int is64 = block_is64((const int*)sidx, 2 * n * 2);
    int gw = (blockIdx.x * blockDim.x + threadIdx.x) >> 5;
    int lane = threadIdx.x & 31;
    if (gw >= n) return;
    int r, c;
    if (is64) {
        longlong2 rc = ((const longlong2*)sidx)[gw];
        r = (int)rc.x; c = (int)rc.y;
    } else {
        int2 rc = ((const int2*)sidx)[gw];
        r = rc.x; c = rc.y;
    }
    if ((unsigned)r >= (unsigned)n || (unsigned)c >= (unsigned)n) return;
    bool act = (lane < FD4);
    float v = sval[gw];
    float4 x = make_float4(0.f, 0.f, 0.f, 0.f);
    if (act) {
        float4 s = ((const float4*)node_f)[(long)c * FD4 + lane];
        x.x = fmaxf(v * s.x, 0.0f);
        x.y = fmaxf(v * s.y, 0.0f);
        x.z = fmaxf(v * s.z, 0.0f);
        x.w = fmaxf(v * s.w, 0.0f);
        g_fa[(long)r * FD4 + lane] = x;
        ((float4*)(out + (long)r * OUTC))[lane] = x;
    }
    eterm_from_regs(g_et_a, r, x, act, lane, (const float4*)as, (const float4*)an);
}

// ---------------- layer: direct-exp softmax + combined-weight aggregate ---
__global__ void __launch_bounds__(256) k_layer(int src, float* __restrict__ out,
                                               const float* __restrict__ as,
                                               const float* __restrict__ an,
                                               int layer, int n) {
    __shared__ float4 s_w4[8][SMW / 2];   // 8 warps x 32 float4 = 4KB
    int wslot = (threadIdx.x >> 5);
    int gw = (blockIdx.x * blockDim.x + threadIdx.x) >> 5;
    int lane = threadIdx.x & 31;
    if (gw >= n) return;
    const float4* feat  = src ? g_fb : g_fa;
    float4* feat_out    = src ? g_fa : g_fb;
    const float4* et_in = src ? g_et_b : g_et_a;
    float4* et_out      = src ? g_et_a : g_et_b;

    int start = gw * CAP;
    int deg   = min(g_deg[gw], CAP);
    int end   = start + deg;
    bool small = (deg <= SMW);

    float4 er = et_in[gw];
    float es0 = er.x, es1 = er.y;

    // pass 1: gather eterm, exp(leaky(score)) -> smem (or g_scbig) + sums
    float sum0 = 0.0f, sum1 = 0.0f;
    {
        float2* sw2 = (float2*)s_w4[wslot];
        float2* sb2 = (float2*)g_scbig;
        for (int j = start + lane; j < end; j += 32) {
            int c = g_csrcol[j];
            float4 ec = et_in[c];
            float w0 = __expf(leaky(es0 + ec.z));
            float w1 = __expf(leaky(es1 + ec.w));
            if (small) sw2[j - start] = make_float2(w0, w1);
            else       sb2[j] = make_float2(w0, w1);
            sum0 += w0;
            sum1 += w1;
        }
    }
#pragma unroll
    for (int off = 16; off > 0; off >>= 1) {
        sum0 += __shfl_xor_sync(0xffffffffu, sum0, off);
        sum1 += __shfl_xor_sync(0xffffffffu, sum1, off);
    }
    // fold the 0.5 head-mean into the normalizers: out = sum_e we * f_e
    // with we = w0e*h0 + w1e*h1  (exact redistribution of the two softmaxes)
    float h0 = sum0 > 0.0f ? 0.5f / sum0 : 0.0f;
    float h1 = sum1 > 0.0f ? 0.5f / sum1 : 0.0f;
    __syncwarp();

    // pass 2: combined-weight aggregation, 4 edges in flight, ONE accumulator
    float4 A = make_float4(0.f, 0.f, 0.f, 0.f);
    bool act = (lane < FD4);

    int j = start;
    for (; j + 4 <= end; j += 4) {
        int i0 = j - start;
        int4 cc = *(const int4*)&g_csrcol[j];
        float4 wA, wB;                     // (w0e0,w1e0,w0e1,w1e1),(e2,e3)
        if (small) {
            wA = s_w4[wslot][i0 >> 1];
            wB = s_w4[wslot][(i0 >> 1) + 1];
        } else {
            wA = g_scbig[(j >> 1)];
            wB = g_scbig[(j >> 1) + 1];
        }
        float we0 = wA.x * h0 + wA.y * h1;
        float we1 = wA.z * h0 + wA.w * h1;
        float we2 = wB.x * h0 + wB.y * h1;
        float we3 = wB.z * h0 + wB.w * h1;
        float4 f0 = make_float4(0.f,0.f,0.f,0.f), f1 = f0, f2 = f0, f3 = f0;
        if (act) {
            f0 = feat[(long)cc.x * FD4 + lane];
            f1 = feat[(long)cc.y * FD4 + lane];
            f2 = feat[(long)cc.z * FD4 + lane];
            f3 = feat[(long)cc.w * FD4 + lane];
        }
        A.x += we0*f0.x + we1*f1.x + we2*f2.x + we3*f3.x;
        A.y += we0*f0.y + we1*f1.y + we2*f2.y + we3*f3.y;
        A.z += we0*f0.z + we1*f1.z + we2*f2.z + we3*f3.z;
        A.w += we0*f0.w + we1*f1.w + we2*f2.w + we3*f3.w;
    }
    for (; j < end; j++) {
        int c0 = g_csrcol[j];
        float2 w0 = small ? ((float2*)s_w4[wslot])[j - start]
                          : ((float2*)g_scbig)[j];
        float we = w0.x * h0 + w0.y * h1;
        float4 f0 = make_float4(0.f,0.f,0.f,0.f);
        if (act) f0 = feat[(long)c0 * FD4 + lane];
        A.x += we*f0.x; A.y += we*f0.y; A.z += we*f0.z; A.w += we*f0.w;
    }

    float4 v = make_float4(0.f, 0.f, 0.f, 0.f);
    if (act) {
        v.x = fmaxf(A.x, 0.0f);
        v.y = fmaxf(A.y, 0.0f);
        v.z = fmaxf(A.z, 0.0f);
        v.w = fmaxf(A.w, 0.0f);
        feat_out[(long)gw * FD4 + lane] = v;
        ((float4*)(out + (long)gw * OUTC + (layer + 1) * FDIM))[lane] = v;
    }
    if (layer + 1 < DEPTH)
        eterm_from_regs(et_out, gw, v, act, lane,
                        (const float4*)as, (const float4*)an);
}

// ---------------- launch ----------------
extern "C" void kernel_launch(void* const* d_in, const int* in_sizes, int n_in,
                              void* d_out, int out_size) {
    const float* node_f = (const float*)d_in[0];
    const void*  adj    = d_in[1];
    const void*  sidx   = d_in[2];
    const float* sval   = (const float*)d_in[3];
    const float* as_k   = (const float*)d_in[4];
    const float* an_k   = (const float*)d_in[5];
    float*       out    = (float*)d_out;

    int n = in_sizes[0] / FDIM;
    int e = in_sizes[1] / 2;
    if (n > NMAX) n = NMAX;
    if (e > EMAX) e = EMAX;

    const int T = 256;
    int gridN = (n + T - 1) / T;
    int gridE = (e + T - 1) / T;
    int gridW = (n + (T / 32) - 1) / (T / 32);

    k_zero<<<gridN, T>>>(n);
    k_scatter<<<gridE, T>>>(adj, e, n);
    k_init<<<gridW, T>>>(node_f, sidx, sval, as_k, an_k, out, n);

    int src = 0;
    for (int d = 0; d < DEPTH; d++) {
        k_layer<<<gridW, T>>>(src, out, as_k, an_k, d, n);
        src ^= 1;
    }
}